// round 16
// baseline (speedup 1.0000x reference)
#include <cuda_runtime.h>
#include <cuda_bf16.h>
#include <cuda.h>
#include <cstdint>

#define BHc 16
#define LNc 2048
#define DMc 256
#define VDc 512
#define LOG2G (-0.15200309344504995f)
#define GINVf (1.1111111111111112f)

#if defined(__CUDA_ARCH_FEAT_SM103_ALL) || defined(__CUDA_ARCH_FEAT_SM100_ALL) || \
    (defined(__CUDA_ARCH_SPECIFIC__) && (__CUDA_ARCH_SPECIFIC__ >= 1000))
#define TC_OK 1
#else
#define TC_OK 0
#endif

// ---------------- scratch (bf16 hi/lo split pairs) -------------------------
__device__ __align__(1024) __nv_bfloat16 g_x_hi [32768u * 256];
__device__ __align__(1024) __nv_bfloat16 g_x_lo [32768u * 256];
__device__ __align__(1024) __nv_bfloat16 g_w_hi [1024u  * 256];
__device__ __align__(1024) __nv_bfloat16 g_w_lo [1024u  * 256];
__device__ __align__(1024) __nv_bfloat16 g_q_hi [32768u * 256];
__device__ __align__(1024) __nv_bfloat16 g_q_lo [32768u * 256];
__device__ __align__(1024) __nv_bfloat16 g_k_hi [32768u * 256];
__device__ __align__(1024) __nv_bfloat16 g_k_lo [32768u * 256];
__device__ __align__(1024) __nv_bfloat16 g_vt_hi[8192u  * 2048];  // [bh*512+n][m]
__device__ __align__(1024) __nv_bfloat16 g_vt_lo[8192u  * 2048];
__device__ __align__(1024) __nv_bfloat16 g_s_hi [(size_t)294912 * 128];
__device__ __align__(1024) __nv_bfloat16 g_s_lo [(size_t)294912 * 128];
__device__ __align__(1024) float2        g_rotT [128 * 2048];     // [j][l] (cos,sin)

// smem layout
// modes 0/1: x/q chunk double-buffer 2x32KB, stream ring 4x32KB
#define XB_OFF     1024
#define WR_OFF     (XB_OFF + 2 * 32768)    // 66560
// mode 2: 2 x 96KB
#define RING2_OFF  1024
#define STG2       98304
#define STAGE_OFF  197632                  // 2 x 16KB staging (one per group)
#define SMEM_TOTAL 230400

// ---------------- small helpers --------------------------------------------
static __device__ __forceinline__ uint32_t s2u(const void* p) {
    uint32_t a;
    asm("{ .reg .u64 t; cvta.to.shared.u64 t, %1; cvt.u32.u64 %0, t; }"
        : "=r"(a) : "l"(p));
    return a;
}
static __device__ __forceinline__ void split2(float x0, float x1,
                                              uint32_t& h, uint32_t& l) {
    asm("cvt.rn.bf16x2.f32 %0, %1, %2;" : "=r"(h) : "f"(x1), "f"(x0));
    float h0 = __uint_as_float(h << 16);
    float h1 = __uint_as_float(h & 0xffff0000u);
    asm("cvt.rn.bf16x2.f32 %0, %1, %2;" : "=r"(l) : "f"(x1 - h1), "f"(x0 - h0));
}
static __device__ __forceinline__ void split1(float x, __nv_bfloat16& h,
                                              __nv_bfloat16& l) {
    h = __float2bfloat16_rn(x);
    l = __float2bfloat16_rn(x - __bfloat162float(h));
}
static __device__ __forceinline__ float joinf(const __nv_bfloat16* hi,
                                              const __nv_bfloat16* lo, size_t i) {
    return __bfloat162float(hi[i]) + __bfloat162float(lo[i]);
}

#if TC_OK
static __device__ __forceinline__ uint64_t mkdesc(uint32_t addr) {
    const uint64_t base = (2ull << 61) | (1ull << 46) | (64ull << 32) | (1ull << 16);
    return base | ((uint64_t)(addr >> 4) & 0x3FFF);
}
static __device__ __forceinline__ void mma_bf16(uint32_t d, uint64_t a, uint64_t b,
                                                uint32_t idesc, uint32_t en) {
    asm volatile(
        "{\n\t.reg .pred p;\n\tsetp.ne.u32 p, %4, 0;\n\t"
        "tcgen05.mma.cta_group::1.kind::f16 [%0], %1, %2, %3, p;\n\t}"
        :: "r"(d), "l"(a), "l"(b), "r"(idesc), "r"(en) : "memory");
}
static __device__ __forceinline__ void tma2d(uint32_t dst, const CUtensorMap* m,
                                             int x, int y, uint32_t mbar) {
    asm volatile(
        "cp.async.bulk.tensor.2d.shared::cta.global.tile.mbarrier::complete_tx::bytes "
        "[%0], [%1, {%2, %3}], [%4];"
        :: "r"(dst), "l"((const void*)m), "r"(x), "r"(y), "r"(mbar) : "memory");
}
static __device__ __forceinline__ void tma_st2d(const CUtensorMap* m,
                                                int x, int y, uint32_t src) {
    asm volatile(
        "cp.async.bulk.tensor.2d.global.shared::cta.tile.bulk_group "
        "[%0, {%1, %2}], [%3];"
        :: "l"((const void*)m), "r"(x), "r"(y), "r"(src) : "memory");
}
#define TC_ALLOC(sm, n)  asm volatile("tcgen05.alloc.cta_group::1.sync.aligned.shared::cta.b32 [%0], %1;" :: "r"(sm), "r"(n) : "memory")
#define TC_DEALLOC(t, n) asm volatile("tcgen05.dealloc.cta_group::1.sync.aligned.b32 %0, %1;" :: "r"(t), "r"(n))
#define TC_RELINQ()      asm volatile("tcgen05.relinquish_alloc_permit.cta_group::1.sync.aligned;")
#define TC_COMMIT(mb)    asm volatile("tcgen05.commit.cta_group::1.mbarrier::arrive::one.shared::cluster.b64 [%0];" :: "r"(mb) : "memory")
#define TC_FENCE_AFTER() asm volatile("tcgen05.fence::after_thread_sync;" ::: "memory")
#define TC_WAIT_LD()     asm volatile("tcgen05.wait::ld.sync.aligned;" ::: "memory")
#define MBAR_INIT(mb, c) asm volatile("mbarrier.init.shared.b64 [%0], %1;" :: "r"(mb), "r"(c) : "memory")
#define EXPECT_TX(mb, n) asm volatile("mbarrier.arrive.expect_tx.shared.b64 _, [%0], %1;" :: "r"(mb), "r"(n) : "memory")
#define FENCE_ASYNC()    asm volatile("fence.proxy.async.shared::cta;" ::: "memory")
#define BARG(id)         asm volatile("bar.sync %0, 128;" :: "r"(id) : "memory")
#define TMA_ST_COMMIT()  asm volatile("cp.async.bulk.commit_group;" ::: "memory")
#define TMA_ST_WAIT0()   asm volatile("cp.async.bulk.wait_group 0;" ::: "memory")

#define MBAR_WAIT(mb, ph) do {                                                   \
    uint32_t _m = (mb), _p = (ph), _d;                                           \
    asm volatile("{\n\t.reg .pred p;\n\t"                                        \
        "mbarrier.try_wait.parity.acquire.cta.shared::cta.b64 p, [%1], %2;\n\t"  \
        "selp.b32 %0, 1, 0, p;\n\t}"                                             \
        : "=r"(_d) : "r"(_m), "r"(_p) : "memory");                               \
    if (!_d) {                                                                   \
        asm volatile("{\n\t.reg .pred P1;\n\t"                                   \
            "W_%=:\n\t"                                                          \
            "mbarrier.try_wait.parity.acquire.cta.shared::cta.b64 P1, [%0], %1, 0x989680;\n\t" \
            "@P1 bra.uni D_%=;\n\tbra.uni W_%=;\n\tD_%=:\n\t}"                   \
            :: "r"(_m), "r"(_p) : "memory");                                     \
    }                                                                            \
} while (0)

#define TC_LD_X32(r, ta)                                                         \
    asm volatile("tcgen05.ld.sync.aligned.32x32b.x32.b32 "                       \
        "{%0,%1,%2,%3,%4,%5,%6,%7,%8,%9,%10,%11,%12,%13,%14,%15,"                \
        "%16,%17,%18,%19,%20,%21,%22,%23,%24,%25,%26,%27,%28,%29,%30,%31}, [%32];" \
        : "=r"((r)[0]),"=r"((r)[1]),"=r"((r)[2]),"=r"((r)[3]),                   \
          "=r"((r)[4]),"=r"((r)[5]),"=r"((r)[6]),"=r"((r)[7]),                   \
          "=r"((r)[8]),"=r"((r)[9]),"=r"((r)[10]),"=r"((r)[11]),                 \
          "=r"((r)[12]),"=r"((r)[13]),"=r"((r)[14]),"=r"((r)[15]),               \
          "=r"((r)[16]),"=r"((r)[17]),"=r"((r)[18]),"=r"((r)[19]),               \
          "=r"((r)[20]),"=r"((r)[21]),"=r"((r)[22]),"=r"((r)[23]),               \
          "=r"((r)[24]),"=r"((r)[25]),"=r"((r)[26]),"=r"((r)[27]),               \
          "=r"((r)[28]),"=r"((r)[29]),"=r"((r)[30]),"=r"((r)[31])                \
        : "r"(ta))

#define IDESC_N128 0x08200490u
#define IDESC_N256 0x08400490u
#endif

// ---------------- merged prep kernel ----------------------------------------
__global__ void __launch_bounds__(256) prep_k(const float* __restrict__ X,
                                              const float* __restrict__ WQ,
                                              const float* __restrict__ WK,
                                              const float* __restrict__ WV) {
    const int bid = blockIdx.x;
    if (bid < 8192) {
        size_t i = ((size_t)bid * 256 + threadIdx.x) * 4;
        float4 v = *(const float4*)(X + i);
        uint32_t h0, h1, l0, l1;
        split2(v.x, v.y, h0, l0);
        split2(v.z, v.w, h1, l1);
        *(uint2*)&g_x_hi[i] = make_uint2(h0, h1);
        *(uint2*)&g_x_lo[i] = make_uint2(l0, l1);
    } else if (bid < 9216) {
        const int n = bid - 8192, k = threadIdx.x;
        const float* src;
        int nn, WN;
        if (n < 256)      { src = WQ; nn = n;       WN = 256; }
        else if (n < 512) { src = WK; nn = n - 256; WN = 256; }
        else              { src = WV; nn = n - 512; WN = 512; }
        float x = src[(size_t)k * WN + nn];
        __nv_bfloat16 h, l;
        split1(x, h, l);
        g_w_hi[(size_t)n * 256 + k] = h;
        g_w_lo[(size_t)n * 256 + k] = l;
    } else {
        const int idx = (bid - 9216) * 256 + threadIdx.x;
        const int j = idx >> 11, l = idx & 2047;
        float theta = exp2f(-(float)j * (13.287712379549449f / 127.0f));
        float sn, cs;
        sincosf((float)l * theta, &sn, &cs);
        g_rotT[idx] = make_float2(cs, sn);
    }
}

// ---------------- pipelined GEMMs -------------------------------------------
// MODE 0: proj. MODE 1: score (+zero tiles for its quarter). MODE 2: vt.
template <int MODE>
__global__ void __launch_bounds__(384, 1)
gemm_p(const __grid_constant__ CUtensorMap tm0, const __grid_constant__ CUtensorMap tm1,
       const __grid_constant__ CUtensorMap tm2, const __grid_constant__ CUtensorMap tm3,
       const __grid_constant__ CUtensorMap tmS0, const __grid_constant__ CUtensorMap tmS1,
       const __grid_constant__ CUtensorMap tmS2, const __grid_constant__ CUtensorMap tmS3,
       const __grid_constant__ CUtensorMap tmS4, const __grid_constant__ CUtensorMap tmS5,
       float* __restrict__ score, float* __restrict__ vtout) {
    const int tid = threadIdx.x;

#if TC_OK
    extern __shared__ char smem[];
    const uint32_t smem_base = s2u(smem);
    const int wid = tid >> 5;

#define B_XF(b) (smem_base + 16  + (b) * 8)
#define B_XE(b) (smem_base + 32  + (b) * 8)
#define B_WF(b) (smem_base + 48  + (b) * 8)
#define B_WE(b) (smem_base + 80  + (b) * 8)
#define B_AF(b) (smem_base + 112 + (b) * 8)
#define XB(b)   (smem_base + XB_OFF + (b) * 32768)
#define WR(b)   (smem_base + WR_OFF + (b) * 32768)

    if (wid == 0) TC_ALLOC(smem_base, 512);
    if (tid == 0) {
#pragma unroll
        for (int b = 0; b < 2; b++) { MBAR_INIT(B_XF(b), 1); MBAR_INIT(B_XE(b), 1); }
#pragma unroll
        for (int b = 0; b < 4; b++) { MBAR_INIT(B_WF(b), 1); MBAR_INIT(B_WE(b), 1); MBAR_INIT(B_AF(b), 1); }
    }
    __syncthreads();
    uint32_t tmem;
    asm volatile("ld.shared.b32 %0, [%1];" : "=r"(tmem) : "r"(smem_base));

    const int grp = (tid >> 7) & 1;
    const int gtid = tid & 127;
    const int growIdx = gtid;
    const uint32_t gstage = smem_base + STAGE_OFF + grp * 16384;
    const int gbar = 1 + grp;

    if constexpr (MODE == 0) {
        const int mt = blockIdx.x >> 1, halfN = blockIdx.x & 1;
        if (tid == 256) {
            auto issueX = [&](int s) {
                const int b = s & 1;
                EXPECT_TX(B_XF(b), 32768);
                tma2d(XB(b),         &tm0, s * 64, mt * 128, B_XF(b));
                tma2d(XB(b) + 16384, &tm1, s * 64, mt * 128, B_XF(b));
            };
            auto issueW = [&](int g) {
                const int b = g & 3, s = g >> 2;
                const int nb = halfN * 4 + (g & 3);
                EXPECT_TX(B_WF(b), 32768);
                tma2d(WR(b),         &tm2, s * 64, nb * 128, B_WF(b));
                tma2d(WR(b) + 16384, &tm3, s * 64, nb * 128, B_WF(b));
            };
            issueX(0); issueX(1);
            for (int g = 0; g < 4; g++) issueW(g);
            int phXF[2] = {0, 0}, phXE[2] = {0, 0};
            int phWF[4] = {0, 0, 0, 0}, phWE[4] = {0, 0, 0, 0};
            for (int g = 0; g < 16; g++) {
                const int s = g >> 2, nb = g & 3, wb = g & 3, xbuf = s & 1;
                if (nb == 0) { MBAR_WAIT(B_XF(xbuf), phXF[xbuf]); phXF[xbuf] ^= 1; }
                MBAR_WAIT(B_WF(wb), phWF[wb]); phWF[wb] ^= 1;
                const uint64_t ah_ = mkdesc(XB(xbuf));
                const uint64_t al_ = mkdesc(XB(xbuf) + 16384);
                const uint64_t bh_ = mkdesc(WR(wb));
                const uint64_t bl_ = mkdesc(WR(wb) + 16384);
                const uint32_t dacc = tmem + nb * 128;
#pragma unroll
                for (int ks = 0; ks < 4; ks++) {
                    mma_bf16(dacc, ah_ + ks * 2, bh_ + ks * 2, IDESC_N128, (s > 0 || ks > 0) ? 1u : 0u);
                    mma_bf16(dacc, ah_ + ks * 2, bl_ + ks * 2, IDESC_N128, 1u);
                    mma_bf16(dacc, al_ + ks * 2, bh_ + ks * 2, IDESC_N128, 1u);
                }
                TC_COMMIT(B_WE(wb));
                if (nb == 3) TC_COMMIT(B_XE(xbuf));
                if (s == 3) TC_COMMIT(B_AF(nb));
                if (g + 4 < 16) { MBAR_WAIT(B_WE(wb), phWE[wb]); phWE[wb] ^= 1; issueW(g + 4); }
                if (nb == 3 && s + 2 < 4) { MBAR_WAIT(B_XE(xbuf), phXE[xbuf]); phXE[xbuf] ^= 1; issueX(s + 2); }
            }
        }
        if (tid < 256) {
            for (int ni = 0; ni < 4; ni++) {
                const int nb = halfN * 4 + ni;
                MBAR_WAIT(B_AF(ni), 0);
                TC_FENCE_AFTER();
#pragma unroll 1
                for (int ch = grp; ch < 4; ch += 2) {
                    uint32_t r[32];
                    TC_LD_X32(r, tmem + ni * 128 + ch * 32);
                    TC_WAIT_LD();
                    __nv_bfloat16* sh_ = (__nv_bfloat16*)(smem + STAGE_OFF + grp * 16384);
                    __nv_bfloat16* sl_ = sh_ + 4096;
                    if (gtid == 0) TMA_ST_WAIT0();
                    BARG(gbar);
                    if (halfN == 0) {
                        const bool isQ = nb < 2;
                        const int colbase = (isQ ? nb : nb - 2) * 128 + ch * 32;
                        const int grow = mt * 128 + growIdx;
                        const int l = grow & (LNc - 1);
                        const float2* rp = g_rotT + ((size_t)(colbase >> 1) << 11) + l;
                        uint32_t hi[16], lo[16];
#pragma unroll
                        for (int c = 0; c < 32; c += 2) {
                            float2 t = rp[(size_t)(c >> 1) << 11];
                            float e = __uint_as_float(r[c]);
                            float o = __uint_as_float(r[c + 1]);
                            float ne, no;
                            if (isQ) { ne = e * t.x - o * t.y; no = o * t.x + e * t.y; }
                            else     { ne = e * t.x + o * t.y; no = o * t.x - e * t.y; }
                            split2(ne, no, hi[c >> 1], lo[c >> 1]);
                        }
#pragma unroll
                        for (int q4 = 0; q4 < 4; q4++) {
                            *(uint4*)&sh_[growIdx * 32 + q4 * 8] = ((uint4*)hi)[q4];
                            *(uint4*)&sl_[growIdx * 32 + q4 * 8] = ((uint4*)lo)[q4];
                        }
                        FENCE_ASYNC();
                        BARG(gbar);
                        if (gtid == 0) {
                            if (isQ) {
                                tma_st2d(&tmS0, colbase, mt * 128, gstage);
                                tma_st2d(&tmS1, colbase, mt * 128, gstage + 8192);
                            } else {
                                tma_st2d(&tmS2, colbase, mt * 128, gstage);
                                tma_st2d(&tmS3, colbase, mt * 128, gstage + 8192);
                            }
                            TMA_ST_COMMIT();
                        }
                    } else {
#pragma unroll
                        for (int c = 0; c < 32; c++) {
                            __nv_bfloat16 h, l;
                            split1(__uint_as_float(r[c]), h, l);
                            sh_[c * 128 + growIdx] = h;
                            sl_[c * 128 + growIdx] = l;
                        }
                        FENCE_ASYNC();
                        BARG(gbar);
                        if (gtid == 0) {
                            const int mloc0 = (mt * 128) & (LNc - 1);
                            const int y = (mt >> 4) * 512 + ni * 128 + ch * 32;
                            tma_st2d(&tmS4, mloc0, y, gstage);
                            tma_st2d(&tmS5, mloc0, y, gstage + 8192);
                            TMA_ST_COMMIT();
                        }
                    }
                }
            }
            if (gtid == 0) TMA_ST_WAIT0();
        }
    } else if constexpr (MODE == 1) {
        const int quarter = blockIdx.x, lb = blockIdx.y, bh = blockIdx.z;
        int mbs[4], nband = 0;
        for (int t = 0; t < 4; t++) {
            const int mb = quarter * 4 + t;
            const int d = lb - mb;
            if (d >= 0 && d <= 8) mbs[nband++] = mb;
        }
        const int S = nband * 4;
        if (tid == 256 && nband > 0) {
            auto issueQ = [&](int s) {
                const int b = s & 1;
                EXPECT_TX(B_XF(b), 32768);
                tma2d(XB(b),         &tm0, s * 64, bh * 2048 + lb * 128, B_XF(b));
                tma2d(XB(b) + 16384, &tm1, s * 64, bh * 2048 + lb * 128, B_XF(b));
            };
            auto issueK = [&](int g) {
                const int b = g & 3;
                const int mb = mbs[g % nband], s = g / nband;
                EXPECT_TX(B_WF(b), 32768);
                tma2d(WR(b),         &tm2, s * 64, bh * 2048 + mb * 128, B_WF(b));
                tma2d(WR(b) + 16384, &tm3, s * 64, bh * 2048 + mb * 128, B_WF(b));
            };
            issueQ(0); issueQ(1);
            const int pre = (S < 4) ? S : 4;
            for (int g = 0; g < pre; g++) issueK(g);
            int phXF[2] = {0, 0}, phXE[2] = {0, 0};
            int phWF[4] = {0, 0, 0, 0}, phWE[4] = {0, 0, 0, 0};
            for (int g = 0; g < S; g++) {
                const int s = g / nband, ti = g % nband, wb = g & 3, xbuf = s & 1;
                if (ti == 0) { MBAR_WAIT(B_XF(xbuf), phXF[xbuf]); phXF[xbuf] ^= 1; }
                MBAR_WAIT(B_WF(wb), phWF[wb]); phWF[wb] ^= 1;
                const uint64_t ah_ = mkdesc(XB(xbuf));
                const uint64_t al_ = mkdesc(XB(xbuf) + 16384);
                const uint64_t bh_ = mkdesc(WR(wb));
                const uint64_t bl_ = mkdesc(WR(wb) + 16384);
                const uint32_t dacc = tmem + ti * 128;
#pragma unroll
                for (int ks = 0; ks < 4; ks++) {
                    mma_bf16(dacc, ah_ + ks * 2, bh_ + ks * 2, IDESC_N128, (s > 0 || ks > 0) ? 1u : 0u);
                    mma_bf16(dacc, ah_ + ks * 2, bl_ + ks * 2, IDESC_N128, 1u);
                    mma_bf16(dacc, al_ + ks * 2, bh_ + ks * 2, IDESC_N128, 1u);
                }
                TC_COMMIT(B_WE(wb));
                if (ti == nband - 1) TC_COMMIT(B_XE(xbuf));
                if (s == 3) TC_COMMIT(B_AF(ti));
                if (g + 4 < S) { MBAR_WAIT(B_WE(wb), phWE[wb]); phWE[wb] ^= 1; issueK(g + 4); }
                if (ti == nband - 1 && s + 2 < 4) {
                    MBAR_WAIT(B_XE(xbuf), phXE[xbuf]); phXE[xbuf] ^= 1;
                    issueQ(s + 2);
                }
            }
        }
        if (tid < 256) {
            // ---- zero tiles for this quarter (moved here from vt kernel) ----
            {
                const float4 z = make_float4(0.f, 0.f, 0.f, 0.f);
                for (int t = 0; t < 4; t++) {
                    const int mb = quarter * 4 + t;
                    const int d = lb - mb;
                    if (d >= 0 && d <= 8) continue;
                    float* base = score + ((size_t)bh * LNc + (size_t)lb * 128) * LNc + mb * 128;
#pragma unroll 4
                    for (int i = 0; i < 16; i++) {
                        const int e = i * 256 + tid;      // e in [0, 4095]
                        const int row = e >> 5, c4 = e & 31;
                        *((float4*)(base + (size_t)row * LNc) + c4) = z;
                    }
                }
            }
            if (nband > 0) {
                const int l = lb * 128 + growIdx;
                const float gpl = exp2f((float)(l + 1) * LOG2G);
                const float scale = 0.0625f / ((1.0f - gpl) * 10.0f);
                for (int ti = 0; ti < nband; ti++) {
                    const int mb = mbs[ti];
                    const int diag = lb - mb;
                    MBAR_WAIT(B_AF(ti), 0);
                    TC_FENCE_AFTER();
#pragma unroll 1
                    for (int ch = grp; ch < 4; ch += 2) {
                        uint32_t r[32];
                        TC_LD_X32(r, tmem + ti * 128 + ch * 32);
                        TC_WAIT_LD();
                        const int m0 = mb * 128 + ch * 32;
                        float v[32];
                        if (m0 > l) {
#pragma unroll
                            for (int c = 0; c < 32; c++) v[c] = 0.f;
                        } else {
                            float w = exp2f((float)(l - m0) * LOG2G) * scale;
#pragma unroll
                            for (int c = 0; c < 32; c++) {
                                v[c] = (m0 + c <= l) ? __uint_as_float(r[c]) * w : 0.f;
                                w *= GINVf;
                            }
                        }
                        uint32_t hi[16], lo[16];
#pragma unroll
                        for (int c = 0; c < 32; c += 2)
                            split2(v[c], v[c + 1], hi[c >> 1], lo[c >> 1]);
                        const int tile9 = (bh * 16 + lb) * 9 + diag;
                        const size_t sbase = ((size_t)tile9 * 128 + growIdx) * 128 + ch * 32;
#pragma unroll
                        for (int q4 = 0; q4 < 4; q4++) {
                            *(uint4*)&g_s_hi[sbase + q4 * 8] = ((uint4*)hi)[q4];
                            *(uint4*)&g_s_lo[sbase + q4 * 8] = ((uint4*)lo)[q4];
                        }
                        if (gtid == 0) TMA_ST_WAIT0();
                        BARG(gbar);
#pragma unroll
                        for (int c4 = 0; c4 < 32; c4 += 4) {
                            uint32_t byte = growIdx * 128 + c4 * 4;
                            uint32_t sw = byte ^ ((byte >> 3) & 0x70);
                            *(float4*)(smem + STAGE_OFF + grp * 16384 + sw) =
                                make_float4(v[c4], v[c4 + 1], v[c4 + 2], v[c4 + 3]);
                        }
                        FENCE_ASYNC();
                        BARG(gbar);
                        if (gtid == 0) {
                            tma_st2d(&tmS0, m0, bh * 2048 + lb * 128, gstage);
                            TMA_ST_COMMIT();
                        }
                    }
                }
                if (gtid == 0) TMA_ST_WAIT0();
            }
        }
    } else {
        // ============================ MODE 2 (vt) ===========================
        const int tile = blockIdx.x;
        const int half = tile & 1, lb = (tile >> 1) & 15, bh = tile >> 5;
        const int dmax = lb < 8 ? lb : 8, mb0 = lb - dmax;
        const int nst = (dmax + 1) * 2;

        if (tid == 256) {
            auto issueStg = [&](int s, int b) {
                const int xa = (s & 1) * 64;
                const int ya = ((bh * 16 + lb) * 9 + (dmax - (s >> 1))) * 128;
                const int xb2 = mb0 * 128 + s * 64;
                const int yb = bh * 512 + half * 256;
                const uint32_t dst = smem_base + RING2_OFF + b * STG2;
                EXPECT_TX(B_WF(b), STG2);
                tma2d(dst,         &tm0, xa, ya, B_WF(b));
                tma2d(dst + 16384, &tm1, xa, ya, B_WF(b));
                tma2d(dst + 32768, &tm2, xb2, yb, B_WF(b));
                tma2d(dst + 65536, &tm3, xb2, yb, B_WF(b));
            };
            const int pre = nst < 2 ? nst : 2;
            for (int s = 0; s < pre; s++) issueStg(s, s);
            int phF[2] = {0, 0}, phE[2] = {0, 0};
            for (int s = 0; s < nst; s++) {
                const int b = s & 1;
                MBAR_WAIT(B_WF(b), phF[b]); phF[b] ^= 1;
                const uint32_t stg = smem_base + RING2_OFF + b * STG2;
                const uint64_t ah  = mkdesc(stg);
                const uint64_t al  = mkdesc(stg + 16384);
                const uint64_t bhd = mkdesc(stg + 32768);
                const uint64_t bld = mkdesc(stg + 65536);
#pragma unroll
                for (int ks = 0; ks < 4; ks++) {
                    mma_bf16(tmem, ah + ks * 2, bhd + ks * 2, IDESC_N256, (s > 0 || ks > 0) ? 1u : 0u);
                    mma_bf16(tmem, ah + ks * 2, bld + ks * 2, IDESC_N256, 1u);
                    mma_bf16(tmem, al + ks * 2, bhd + ks * 2, IDESC_N256, 1u);
                }
                TC_COMMIT(B_WE(b));
                if (s + 2 < nst) {
                    MBAR_WAIT(B_WE(b), phE[b]); phE[b] ^= 1;
                    issueStg(s + 2, b);
                }
            }
            TC_COMMIT(B_AF(0));
        }
        if (tid < 256) {
            MBAR_WAIT(B_AF(0), 0);
            TC_FENCE_AFTER();
#pragma unroll 1
            for (int ch = grp; ch < 8; ch += 2) {
                uint32_t r[32];
                TC_LD_X32(r, tmem + ch * 32);
                TC_WAIT_LD();
                if (gtid == 0) TMA_ST_WAIT0();
                BARG(gbar);
#pragma unroll
                for (int c4 = 0; c4 < 32; c4 += 4) {
                    uint32_t byte = growIdx * 128 + c4 * 4;
                    uint32_t sw = byte ^ ((byte >> 3) & 0x70);
                    *(float4*)(smem + STAGE_OFF + grp * 16384 + sw) = make_float4(
                        __uint_as_float(r[c4]),     __uint_as_float(r[c4 + 1]),
                        __uint_as_float(r[c4 + 2]), __uint_as_float(r[c4 + 3]));
                }
                FENCE_ASYNC();
                BARG(gbar);
                if (gtid == 0) {
                    tma_st2d(&tmS0, half * 256 + ch * 32, bh * 2048 + lb * 128, gstage);
                    TMA_ST_COMMIT();
                }
            }
            if (gtid == 0) TMA_ST_WAIT0();
        }
    }

    __syncthreads();
    if (wid == 0) {
        TC_RELINQ();
        TC_DEALLOC(tmem, 512);
    }

#else
    // ---------------- correct (slow) SIMT fallback ---------------------------
    if (tid >= 256) return;
    if constexpr (MODE == 0) {
        const int mt = blockIdx.x >> 1, halfN = blockIdx.x & 1;
        for (int ni = 0; ni < 4; ni++) {
            const int nb = halfN * 4 + ni;
            if (nb < 4) {
                const bool isQ = nb < 2;
                const int colbase = (isQ ? nb : nb - 2) * 128;
                for (int e = tid; e < 128 * 64; e += 256) {
                    const int i = e >> 6, j = (e & 63) * 2;
                    float a0 = 0.f, a1 = 0.f;
                    const size_t ra = (size_t)(mt * 128 + i) * 256;
                    const size_t rb0 = (size_t)(nb * 128 + j) * 256;
#pragma unroll 4
                    for (int k = 0; k < 256; k++) {
                        float xv = joinf(g_x_hi, g_x_lo, ra + k);
                        a0 += xv * joinf(g_w_hi, g_w_lo, rb0 + k);
                        a1 += xv * joinf(g_w_hi, g_w_lo, rb0 + 256 + k);
                    }
                    const int l = (mt * 128 + i) & (LNc - 1);
                    const int col = colbase + j;
                    float theta = exp2f(-(float)(col >> 1) * (13.287712379549449f / 127.0f));
                    float sn, cs;
                    sincosf((float)l * theta, &sn, &cs);
                    float ne, no;
                    if (isQ) { ne = a0 * cs - a1 * sn; no = a1 * cs + a0 * sn; }
                    else     { ne = a0 * cs + a1 * sn; no = a1 * cs - a0 * sn; }
                    __nv_bfloat16 h0, l0, h1, l1;
                    split1(ne, h0, l0); split1(no, h1, l1);
                    __nv_bfloat16* dh = isQ ? g_q_hi : g_k_hi;
                    __nv_bfloat16* dl = isQ ? g_q_lo : g_k_lo;
                    const size_t bidx = (size_t)(mt * 128 + i) * 256 + col;
                    dh[bidx] = h0; dh[bidx + 1] = h1;
                    dl[bidx] = l0; dl[bidx + 1] = l1;
                }
            } else {
                for (int e = tid; e < 128 * 128; e += 256) {
                    const int i = e >> 7, j = e & 127;
                    float a0 = 0.f;
                    const size_t ra = (size_t)(mt * 128 + i) * 256;
                    const size_t rb = (size_t)(nb * 128 + j) * 256;
#pragma unroll 4
                    for (int k = 0; k < 256; k++)
                        a0 += joinf(g_x_hi, g_x_lo, ra + k) * joinf(g_w_hi, g_w_lo, rb + k);
                    const int mrow = mt * 128 + i;
                    const int bhv = mrow >> 11, mloc = mrow & (LNc - 1);
                    __nv_bfloat16 h, l;
                    split1(a0, h, l);
                    const size_t idx = ((size_t)bhv * 512 + (nb - 4) * 128 + j) * 2048 + mloc;
                    g_vt_hi[idx] = h; g_vt_lo[idx] = l;
                }
            }
        }
    } else if constexpr (MODE == 1) {
        const int quarter = blockIdx.x, lb = blockIdx.y, bh = blockIdx.z;
        for (int t = 0; t < 4; t++) {
            const int mb = quarter * 4 + t;
            const int d = lb - mb;
            if (d < 0 || d > 8) {
                float* base = score + ((size_t)bh * LNc + (size_t)lb * 128) * LNc + mb * 128;
                for (int e = tid; e < 128 * 128; e += 256) {
                    const int i = e >> 7, j = e & 127;
                    base[(size_t)i * LNc + j] = 0.f;
                }
                continue;
            }
            for (int e = tid; e < 128 * 128; e += 256) {
                const int i = e >> 7, j = e & 127;
                float acc = 0.f;
                const size_t ra = ((size_t)bh * 2048 + lb * 128 + i) * 256;
                const size_t rb = ((size_t)bh * 2048 + mb * 128 + j) * 256;
#pragma unroll 4
                for (int k = 0; k < 256; k++)
                    acc += joinf(g_q_hi, g_q_lo, ra + k) * joinf(g_k_hi, g_k_lo, rb + k);
                const int l = lb * 128 + i, m = mb * 128 + j;
                const float gpl = exp2f((float)(l + 1) * LOG2G);
                const float scale = 0.0625f / ((1.0f - gpl) * 10.0f);
                float w = (m <= l) ? exp2f((float)(l - m) * LOG2G) * scale : 0.f;
                float v = acc * w;
                score[((size_t)bh * LNc + l) * LNc + m] = v;
                __nv_bfloat16 h, lo_;
                split1(v, h, lo_);
                const size_t sbase = ((size_t)((bh * 16 + lb) * 9 + d) * 128 + i) * 128 + j;
                g_s_hi[sbase] = h; g_s_lo[sbase] = lo_;
            }
        }
    } else {
        const int tile = blockIdx.x;
        const int half = tile & 1, lb = (tile >> 1) & 15, bh = tile >> 5;
        const int dmax = lb < 8 ? lb : 8, mb0 = lb - dmax;
        const int Kl = (dmax + 1) * 128;
        for (int e = tid; e < 128 * 256; e += 256) {
            const int i = e >> 8, j = e & 255;
            float acc = 0.f;
            const size_t rb = ((size_t)bh * 512 + half * 256 + j) * 2048 + mb0 * 128;
#pragma unroll 4
            for (int k = 0; k < Kl; k++) {
                const size_t ra = ((size_t)((bh * 16 + lb) * 9 + (dmax - (k >> 7))) * 128 + i) * 128 + (k & 127);
                acc += joinf(g_s_hi, g_s_lo, ra) * joinf(g_vt_hi, g_vt_lo, rb + k);
            }
            vtout[((size_t)bh * LNc + lb * 128 + i) * VDc + half * 256 + j] = acc;
        }
    }
#endif
}

// ---------------- host ------------------------------------------------------
typedef CUresult (*EncodeFn)(CUtensorMap*, CUtensorMapDataType, cuuint32_t, void*,
                             const cuuint64_t*, const cuuint64_t*, const cuuint32_t*,
                             const cuuint32_t*, CUtensorMapInterleave, CUtensorMapSwizzle,
                             CUtensorMapL2promotion, CUtensorMapFloatOOBfill);

static void make_map(EncodeFn fn, CUtensorMap* m, void* base, CUtensorMapDataType dt,
                     uint64_t d0, uint64_t d1, uint64_t strideB,
                     uint32_t box0, uint32_t box1, CUtensorMapSwizzle sw) {
    cuuint64_t dims[2]    = {d0, d1};
    cuuint64_t strides[1] = {strideB};
    cuuint32_t box[2]     = {box0, box1};
    cuuint32_t es[2]      = {1, 1};
    fn(m, dt, 2, base, dims, strides, box, es,
       CU_TENSOR_MAP_INTERLEAVE_NONE, sw,
       CU_TENSOR_MAP_L2_PROMOTION_L2_128B, CU_TENSOR_MAP_FLOAT_OOB_FILL_NONE);
}

extern "C" void kernel_launch(void* const* d_in, const int* in_sizes, int n_in,
                              void* d_out, int out_size) {
    const float* X  = (const float*)d_in[0];
    const float* WQ = (const float*)d_in[1];
    const float* WK = (const float*)d_in[2];
    const float* WV = (const float*)d_in[3];

    float* out       = (float*)d_out;
    float* out_vt    = out;
    float* out_score = out + (size_t)BHc * LNc * VDc;

    EncodeFn enc = nullptr;
    cudaDriverEntryPointQueryResult qr;
    cudaGetDriverEntryPoint("cuTensorMapEncodeTiled", (void**)&enc,
                            cudaEnableDefault, &qr);

    void *xh, *xl, *wh, *wl, *qh, *ql, *kh, *kl, *vh, *vl, *sh, *sl;
    cudaGetSymbolAddress(&xh, g_x_hi);  cudaGetSymbolAddress(&xl, g_x_lo);
    cudaGetSymbolAddress(&wh, g_w_hi);  cudaGetSymbolAddress(&wl, g_w_lo);
    cudaGetSymbolAddress(&qh, g_q_hi);  cudaGetSymbolAddress(&ql, g_q_lo);
    cudaGetSymbolAddress(&kh, g_k_hi);  cudaGetSymbolAddress(&kl, g_k_lo);
    cudaGetSymbolAddress(&vh, g_vt_hi); cudaGetSymbolAddress(&vl, g_vt_lo);
    cudaGetSymbolAddress(&sh, g_s_hi);  cudaGetSymbolAddress(&sl, g_s_lo);

    const CUtensorMapDataType BF = CU_TENSOR_MAP_DATA_TYPE_BFLOAT16;
    const CUtensorMapDataType F32 = CU_TENSOR_MAP_DATA_TYPE_FLOAT32;
    const CUtensorMapSwizzle SW = CU_TENSOR_MAP_SWIZZLE_128B;
    const CUtensorMapSwizzle NO = CU_TENSOR_MAP_SWIZZLE_NONE;

    CUtensorMap mxh, mxl, mwh, mwl, mqh, mql, mkh, mkl, mvh, mvl, msh, msl;
    make_map(enc, &mxh, xh, BF, 256, 32768, 512, 64, 128, SW);
    make_map(enc, &mxl, xl, BF, 256, 32768, 512, 64, 128, SW);
    make_map(enc, &mwh, wh, BF, 256, 1024, 512, 64, 128, SW);
    make_map(enc, &mwl, wl, BF, 256, 1024, 512, 64, 128, SW);
    make_map(enc, &mqh, qh, BF, 256, 32768, 512, 64, 128, SW);
    make_map(enc, &mql, ql, BF, 256, 32768, 512, 64, 128, SW);
    make_map(enc, &mkh, kh, BF, 256, 32768, 512, 64, 128, SW);
    make_map(enc, &mkl, kl, BF, 256, 32768, 512, 64, 128, SW);
    make_map(enc, &mvh, vh, BF, 2048, 8192, 4096, 64, 256, SW);
    make_map(enc, &mvl, vl, BF, 2048, 8192, 4096, 64, 256, SW);
    make_map(enc, &msh, sh, BF, 128, 294912, 256, 64, 128, SW);
    make_map(enc, &msl, sl, BF, 128, 294912, 256, 64, 128, SW);
    CUtensorMap sQh, sQl, sKh, sKl, sVh, sVl, sSc, sVt;
    make_map(enc, &sQh, qh, BF, 256, 32768, 512, 32, 128, NO);
    make_map(enc, &sQl, ql, BF, 256, 32768, 512, 32, 128, NO);
    make_map(enc, &sKh, kh, BF, 256, 32768, 512, 32, 128, NO);
    make_map(enc, &sKl, kl, BF, 256, 32768, 512, 32, 128, NO);
    make_map(enc, &sVh, vh, BF, 2048, 8192, 4096, 128, 32, NO);
    make_map(enc, &sVl, vl, BF, 2048, 8192, 4096, 128, 32, NO);
    make_map(enc, &sSc, out_score, F32, 2048, 32768, 8192, 32, 128, SW);
    make_map(enc, &sVt, out_vt,    F32, 512, 32768, 2048, 32, 128, SW);

    cudaFuncSetAttribute(gemm_p<0>, cudaFuncAttributeMaxDynamicSharedMemorySize, SMEM_TOTAL);
    cudaFuncSetAttribute(gemm_p<1>, cudaFuncAttributeMaxDynamicSharedMemorySize, SMEM_TOTAL);
    cudaFuncSetAttribute(gemm_p<2>, cudaFuncAttributeMaxDynamicSharedMemorySize, SMEM_TOTAL);

    prep_k<<<10240, 256>>>(X, WQ, WK, WV);
    gemm_p<0><<<512, 384, SMEM_TOTAL>>>(mxh, mxl, mwh, mwl,
                                        sQh, sQl, sKh, sKl, sVh, sVl,
                                        nullptr, nullptr);
    gemm_p<1><<<dim3(4, 16, 16), 384, SMEM_TOTAL>>>(mqh, mql, mkh, mkl,
                                                    sSc, sSc, sSc, sSc, sSc, sSc,
                                                    out_score, nullptr);
    gemm_p<2><<<512, 384, SMEM_TOTAL>>>(msh, msl, mvh, mvl,
                                        sVt, sVt, sVt, sVt, sVt, sVt,
                                        out_score, out_vt);
}

// round 17
// speedup vs baseline: 1.0489x; 1.0489x over previous
#include <cuda_runtime.h>
#include <cuda_bf16.h>
#include <cuda.h>
#include <cstdint>

#define BHc 16
#define LNc 2048
#define DMc 256
#define VDc 512
#define LOG2G (-0.15200309344504995f)
#define GINVf (1.1111111111111112f)

#if defined(__CUDA_ARCH_FEAT_SM103_ALL) || defined(__CUDA_ARCH_FEAT_SM100_ALL) || \
    (defined(__CUDA_ARCH_SPECIFIC__) && (__CUDA_ARCH_SPECIFIC__ >= 1000))
#define TC_OK 1
#else
#define TC_OK 0
#endif

// ---------------- scratch (bf16 hi/lo split pairs) -------------------------
__device__ __align__(1024) __nv_bfloat16 g_x_hi [32768u * 256];
__device__ __align__(1024) __nv_bfloat16 g_x_lo [32768u * 256];
__device__ __align__(1024) __nv_bfloat16 g_w_hi [1024u  * 256];
__device__ __align__(1024) __nv_bfloat16 g_w_lo [1024u  * 256];
__device__ __align__(1024) __nv_bfloat16 g_q_hi [32768u * 256];
__device__ __align__(1024) __nv_bfloat16 g_q_lo [32768u * 256];
__device__ __align__(1024) __nv_bfloat16 g_k_hi [32768u * 256];
__device__ __align__(1024) __nv_bfloat16 g_k_lo [32768u * 256];
__device__ __align__(1024) __nv_bfloat16 g_vt_hi[8192u  * 2048];  // [bh*512+n][m]
__device__ __align__(1024) __nv_bfloat16 g_vt_lo[8192u  * 2048];
__device__ __align__(1024) __nv_bfloat16 g_s_hi [(size_t)294912 * 128];
__device__ __align__(1024) __nv_bfloat16 g_s_lo [(size_t)294912 * 128];
__device__ __align__(1024) float2        g_rotT [128 * 2048];     // [j][l] (cos,sin)

// dependency flags (zeroed by prep each launch)
__device__ int g_f_qk[256];   // proj (mt, halfN=0) done -> q,k rows of mt ready
__device__ int g_f_vt[256];   // proj (mt, halfN=1) done -> v^T cols of mt ready
__device__ int g_f_s [256];   // score quarters done per (bh*16+lb), counts to 4

// smem layout
#define XB_OFF     1024
#define WR_OFF     (XB_OFF + 2 * 32768)    // 66560
#define RING2_OFF  1024
#define STG2       98304
#define STAGE_OFF  197632                  // 2 x 16KB staging (one per group)
#define SMEM_TOTAL 230400

// ---------------- small helpers --------------------------------------------
static __device__ __forceinline__ uint32_t s2u(const void* p) {
    uint32_t a;
    asm("{ .reg .u64 t; cvta.to.shared.u64 t, %1; cvt.u32.u64 %0, t; }"
        : "=r"(a) : "l"(p));
    return a;
}
static __device__ __forceinline__ void split2(float x0, float x1,
                                              uint32_t& h, uint32_t& l) {
    asm("cvt.rn.bf16x2.f32 %0, %1, %2;" : "=r"(h) : "f"(x1), "f"(x0));
    float h0 = __uint_as_float(h << 16);
    float h1 = __uint_as_float(h & 0xffff0000u);
    asm("cvt.rn.bf16x2.f32 %0, %1, %2;" : "=r"(l) : "f"(x1 - h1), "f"(x0 - h0));
}
static __device__ __forceinline__ void split1(float x, __nv_bfloat16& h,
                                              __nv_bfloat16& l) {
    h = __float2bfloat16_rn(x);
    l = __float2bfloat16_rn(x - __bfloat162float(h));
}
static __device__ __forceinline__ float joinf(const __nv_bfloat16* hi,
                                              const __nv_bfloat16* lo, size_t i) {
    return __bfloat162float(hi[i]) + __bfloat162float(lo[i]);
}
static __device__ __forceinline__ void spin_ge(int* p, int want) {
    volatile int* vp = p;
    while (*vp < want) __nanosleep(64);
}

#if TC_OK
static __device__ __forceinline__ uint64_t mkdesc(uint32_t addr) {
    const uint64_t base = (2ull << 61) | (1ull << 46) | (64ull << 32) | (1ull << 16);
    return base | ((uint64_t)(addr >> 4) & 0x3FFF);
}
static __device__ __forceinline__ void mma_bf16(uint32_t d, uint64_t a, uint64_t b,
                                                uint32_t idesc, uint32_t en) {
    asm volatile(
        "{\n\t.reg .pred p;\n\tsetp.ne.u32 p, %4, 0;\n\t"
        "tcgen05.mma.cta_group::1.kind::f16 [%0], %1, %2, %3, p;\n\t}"
        :: "r"(d), "l"(a), "l"(b), "r"(idesc), "r"(en) : "memory");
}
static __device__ __forceinline__ void tma2d(uint32_t dst, const CUtensorMap* m,
                                             int x, int y, uint32_t mbar) {
    asm volatile(
        "cp.async.bulk.tensor.2d.shared::cta.global.tile.mbarrier::complete_tx::bytes "
        "[%0], [%1, {%2, %3}], [%4];"
        :: "r"(dst), "l"((const void*)m), "r"(x), "r"(y), "r"(mbar) : "memory");
}
static __device__ __forceinline__ void tma_st2d(const CUtensorMap* m,
                                                int x, int y, uint32_t src) {
    asm volatile(
        "cp.async.bulk.tensor.2d.global.shared::cta.tile.bulk_group "
        "[%0, {%1, %2}], [%3];"
        :: "l"((const void*)m), "r"(x), "r"(y), "r"(src) : "memory");
}
#define TC_ALLOC(sm, n)  asm volatile("tcgen05.alloc.cta_group::1.sync.aligned.shared::cta.b32 [%0], %1;" :: "r"(sm), "r"(n) : "memory")
#define TC_DEALLOC(t, n) asm volatile("tcgen05.dealloc.cta_group::1.sync.aligned.b32 %0, %1;" :: "r"(t), "r"(n))
#define TC_RELINQ()      asm volatile("tcgen05.relinquish_alloc_permit.cta_group::1.sync.aligned;")
#define TC_COMMIT(mb)    asm volatile("tcgen05.commit.cta_group::1.mbarrier::arrive::one.shared::cluster.b64 [%0];" :: "r"(mb) : "memory")
#define TC_FENCE_AFTER() asm volatile("tcgen05.fence::after_thread_sync;" ::: "memory")
#define TC_WAIT_LD()     asm volatile("tcgen05.wait::ld.sync.aligned;" ::: "memory")
#define MBAR_INIT(mb, c) asm volatile("mbarrier.init.shared.b64 [%0], %1;" :: "r"(mb), "r"(c) : "memory")
#define EXPECT_TX(mb, n) asm volatile("mbarrier.arrive.expect_tx.shared.b64 _, [%0], %1;" :: "r"(mb), "r"(n) : "memory")
#define FENCE_ASYNC()    asm volatile("fence.proxy.async.shared::cta;" ::: "memory")
#define BARG(id)         asm volatile("bar.sync %0, 128;" :: "r"(id) : "memory")
#define TMA_ST_COMMIT()  asm volatile("cp.async.bulk.commit_group;" ::: "memory")
#define TMA_ST_WAIT0()   asm volatile("cp.async.bulk.wait_group 0;" ::: "memory")

#define MBAR_WAIT(mb, ph) do {                                                   \
    uint32_t _m = (mb), _p = (ph), _d;                                           \
    asm volatile("{\n\t.reg .pred p;\n\t"                                        \
        "mbarrier.try_wait.parity.acquire.cta.shared::cta.b64 p, [%1], %2;\n\t"  \
        "selp.b32 %0, 1, 0, p;\n\t}"                                             \
        : "=r"(_d) : "r"(_m), "r"(_p) : "memory");                               \
    if (!_d) {                                                                   \
        asm volatile("{\n\t.reg .pred P1;\n\t"                                   \
            "W_%=:\n\t"                                                          \
            "mbarrier.try_wait.parity.acquire.cta.shared::cta.b64 P1, [%0], %1, 0x989680;\n\t" \
            "@P1 bra.uni D_%=;\n\tbra.uni W_%=;\n\tD_%=:\n\t}"                   \
            :: "r"(_m), "r"(_p) : "memory");                                     \
    }                                                                            \
} while (0)

#define TC_LD_X32(r, ta)                                                         \
    asm volatile("tcgen05.ld.sync.aligned.32x32b.x32.b32 "                       \
        "{%0,%1,%2,%3,%4,%5,%6,%7,%8,%9,%10,%11,%12,%13,%14,%15,"                \
        "%16,%17,%18,%19,%20,%21,%22,%23,%24,%25,%26,%27,%28,%29,%30,%31}, [%32];" \
        : "=r"((r)[0]),"=r"((r)[1]),"=r"((r)[2]),"=r"((r)[3]),                   \
          "=r"((r)[4]),"=r"((r)[5]),"=r"((r)[6]),"=r"((r)[7]),                   \
          "=r"((r)[8]),"=r"((r)[9]),"=r"((r)[10]),"=r"((r)[11]),                 \
          "=r"((r)[12]),"=r"((r)[13]),"=r"((r)[14]),"=r"((r)[15]),               \
          "=r"((r)[16]),"=r"((r)[17]),"=r"((r)[18]),"=r"((r)[19]),               \
          "=r"((r)[20]),"=r"((r)[21]),"=r"((r)[22]),"=r"((r)[23]),               \
          "=r"((r)[24]),"=r"((r)[25]),"=r"((r)[26]),"=r"((r)[27]),               \
          "=r"((r)[28]),"=r"((r)[29]),"=r"((r)[30]),"=r"((r)[31])                \
        : "r"(ta))

#define IDESC_N128 0x08200490u
#define IDESC_N256 0x08400490u
#endif

// ---------------- merged prep kernel (also zeroes flags) --------------------
__global__ void __launch_bounds__(256) prep_k(const float* __restrict__ X,
                                              const float* __restrict__ WQ,
                                              const float* __restrict__ WK,
                                              const float* __restrict__ WV) {
    const int bid = blockIdx.x;
    if (bid < 8192) {
        size_t i = ((size_t)bid * 256 + threadIdx.x) * 4;
        float4 v = *(const float4*)(X + i);
        uint32_t h0, h1, l0, l1;
        split2(v.x, v.y, h0, l0);
        split2(v.z, v.w, h1, l1);
        *(uint2*)&g_x_hi[i] = make_uint2(h0, h1);
        *(uint2*)&g_x_lo[i] = make_uint2(l0, l1);
    } else if (bid < 9216) {
        const int n = bid - 8192, k = threadIdx.x;
        const float* src;
        int nn, WN;
        if (n < 256)      { src = WQ; nn = n;       WN = 256; }
        else if (n < 512) { src = WK; nn = n - 256; WN = 256; }
        else              { src = WV; nn = n - 512; WN = 512; }
        float x = src[(size_t)k * WN + nn];
        __nv_bfloat16 h, l;
        split1(x, h, l);
        g_w_hi[(size_t)n * 256 + k] = h;
        g_w_lo[(size_t)n * 256 + k] = l;
    } else if (bid < 10240) {
        const int idx = (bid - 9216) * 256 + threadIdx.x;
        const int j = idx >> 11, l = idx & 2047;
        float theta = exp2f(-(float)j * (13.287712379549449f / 127.0f));
        float sn, cs;
        sincosf((float)l * theta, &sn, &cs);
        g_rotT[idx] = make_float2(cs, sn);
    } else {
        // zero dependency flags (graph replays re-run this each iteration)
        const int t = threadIdx.x;
        g_f_qk[t] = 0;
        g_f_vt[t] = 0;
        g_f_s[t]  = 0;
    }
}

// ---------------- fused mega-kernel: proj | score | vt ----------------------
// grid 2048, 384 threads. bid<512: proj (mt,halfN). bid<1536: score
// (quarter,lb,bh). else: vt (half,lb,bh). Cross-stage deps via flag spins
// (all deps have strictly smaller bids -> deadlock-free under in-order
// dispatch). Inner pipelines identical to the 307us round-15 kernel.
__global__ void __launch_bounds__(384, 1)
mega(const __grid_constant__ CUtensorMap mxh, const __grid_constant__ CUtensorMap mxl,
     const __grid_constant__ CUtensorMap mwh, const __grid_constant__ CUtensorMap mwl,
     const __grid_constant__ CUtensorMap mqh, const __grid_constant__ CUtensorMap mql,
     const __grid_constant__ CUtensorMap mkh, const __grid_constant__ CUtensorMap mkl,
     const __grid_constant__ CUtensorMap msh, const __grid_constant__ CUtensorMap msl,
     const __grid_constant__ CUtensorMap mvh, const __grid_constant__ CUtensorMap mvl,
     const __grid_constant__ CUtensorMap sQh, const __grid_constant__ CUtensorMap sQl,
     const __grid_constant__ CUtensorMap sKh, const __grid_constant__ CUtensorMap sKl,
     const __grid_constant__ CUtensorMap sVh, const __grid_constant__ CUtensorMap sVl,
     const __grid_constant__ CUtensorMap sSc, const __grid_constant__ CUtensorMap sVt,
     float* __restrict__ score, float* __restrict__ vtout) {
    const int tid = threadIdx.x;
    const int bid = blockIdx.x;
    const int mode = (bid < 512) ? 0 : (bid < 1536) ? 1 : 2;

#if TC_OK
    extern __shared__ char smem[];
    const uint32_t smem_base = s2u(smem);
    const int wid = tid >> 5;

#define B_XF(b) (smem_base + 16  + (b) * 8)
#define B_XE(b) (smem_base + 32  + (b) * 8)
#define B_WF(b) (smem_base + 48  + (b) * 8)
#define B_WE(b) (smem_base + 80  + (b) * 8)
#define B_AF(b) (smem_base + 112 + (b) * 8)
#define XB(b)   (smem_base + XB_OFF + (b) * 32768)
#define WR(b)   (smem_base + WR_OFF + (b) * 32768)

    if (wid == 0) TC_ALLOC(smem_base, 512);
    if (tid == 0) {
#pragma unroll
        for (int b = 0; b < 2; b++) { MBAR_INIT(B_XF(b), 1); MBAR_INIT(B_XE(b), 1); }
#pragma unroll
        for (int b = 0; b < 4; b++) { MBAR_INIT(B_WF(b), 1); MBAR_INIT(B_WE(b), 1); MBAR_INIT(B_AF(b), 1); }
    }
    __syncthreads();
    uint32_t tmem;
    asm volatile("ld.shared.b32 %0, [%1];" : "=r"(tmem) : "r"(smem_base));

    const int grp = (tid >> 7) & 1;
    const int gtid = tid & 127;
    const int growIdx = gtid;
    const uint32_t gstage = smem_base + STAGE_OFF + grp * 16384;
    const int gbar = 1 + grp;

    if (mode == 0) {
        const int mt = bid >> 1, halfN = bid & 1;
        if (tid == 256) {
            auto issueX = [&](int s) {
                const int b = s & 1;
                EXPECT_TX(B_XF(b), 32768);
                tma2d(XB(b),         &mxh, s * 64, mt * 128, B_XF(b));
                tma2d(XB(b) + 16384, &mxl, s * 64, mt * 128, B_XF(b));
            };
            auto issueW = [&](int g) {
                const int b = g & 3, s = g >> 2;
                const int nb = halfN * 4 + (g & 3);
                EXPECT_TX(B_WF(b), 32768);
                tma2d(WR(b),         &mwh, s * 64, nb * 128, B_WF(b));
                tma2d(WR(b) + 16384, &mwl, s * 64, nb * 128, B_WF(b));
            };
            issueX(0); issueX(1);
            for (int g = 0; g < 4; g++) issueW(g);
            int phXF[2] = {0, 0}, phXE[2] = {0, 0};
            int phWF[4] = {0, 0, 0, 0}, phWE[4] = {0, 0, 0, 0};
            for (int g = 0; g < 16; g++) {
                const int s = g >> 2, nb = g & 3, wb = g & 3, xbuf = s & 1;
                if (nb == 0) { MBAR_WAIT(B_XF(xbuf), phXF[xbuf]); phXF[xbuf] ^= 1; }
                MBAR_WAIT(B_WF(wb), phWF[wb]); phWF[wb] ^= 1;
                const uint64_t ah_ = mkdesc(XB(xbuf));
                const uint64_t al_ = mkdesc(XB(xbuf) + 16384);
                const uint64_t bh_ = mkdesc(WR(wb));
                const uint64_t bl_ = mkdesc(WR(wb) + 16384);
                const uint32_t dacc = tmem + nb * 128;
#pragma unroll
                for (int ks = 0; ks < 4; ks++) {
                    mma_bf16(dacc, ah_ + ks * 2, bh_ + ks * 2, IDESC_N128, (s > 0 || ks > 0) ? 1u : 0u);
                    mma_bf16(dacc, ah_ + ks * 2, bl_ + ks * 2, IDESC_N128, 1u);
                    mma_bf16(dacc, al_ + ks * 2, bh_ + ks * 2, IDESC_N128, 1u);
                }
                TC_COMMIT(B_WE(wb));
                if (nb == 3) TC_COMMIT(B_XE(xbuf));
                if (s == 3) TC_COMMIT(B_AF(nb));
                if (g + 4 < 16) { MBAR_WAIT(B_WE(wb), phWE[wb]); phWE[wb] ^= 1; issueW(g + 4); }
                if (nb == 3 && s + 2 < 4) { MBAR_WAIT(B_XE(xbuf), phXE[xbuf]); phXE[xbuf] ^= 1; issueX(s + 2); }
            }
        }
        if (tid < 256) {
            for (int ni = 0; ni < 4; ni++) {
                const int nb = halfN * 4 + ni;
                MBAR_WAIT(B_AF(ni), 0);
                TC_FENCE_AFTER();
#pragma unroll 1
                for (int ch = grp; ch < 4; ch += 2) {
                    uint32_t r[32];
                    TC_LD_X32(r, tmem + ni * 128 + ch * 32);
                    TC_WAIT_LD();
                    __nv_bfloat16* sh_ = (__nv_bfloat16*)(smem + STAGE_OFF + grp * 16384);
                    __nv_bfloat16* sl_ = sh_ + 4096;
                    if (gtid == 0) TMA_ST_WAIT0();
                    BARG(gbar);
                    if (halfN == 0) {
                        const bool isQ = nb < 2;
                        const int colbase = (isQ ? nb : nb - 2) * 128 + ch * 32;
                        const int grow = mt * 128 + growIdx;
                        const int l = grow & (LNc - 1);
                        const float2* rp = g_rotT + ((size_t)(colbase >> 1) << 11) + l;
                        uint32_t hi[16], lo[16];
#pragma unroll
                        for (int c = 0; c < 32; c += 2) {
                            float2 t = rp[(size_t)(c >> 1) << 11];
                            float e = __uint_as_float(r[c]);
                            float o = __uint_as_float(r[c + 1]);
                            float ne, no;
                            if (isQ) { ne = e * t.x - o * t.y; no = o * t.x + e * t.y; }
                            else     { ne = e * t.x + o * t.y; no = o * t.x - e * t.y; }
                            split2(ne, no, hi[c >> 1], lo[c >> 1]);
                        }
#pragma unroll
                        for (int q4 = 0; q4 < 4; q4++) {
                            *(uint4*)&sh_[growIdx * 32 + q4 * 8] = ((uint4*)hi)[q4];
                            *(uint4*)&sl_[growIdx * 32 + q4 * 8] = ((uint4*)lo)[q4];
                        }
                        FENCE_ASYNC();
                        BARG(gbar);
                        if (gtid == 0) {
                            if (isQ) {
                                tma_st2d(&sQh, colbase, mt * 128, gstage);
                                tma_st2d(&sQl, colbase, mt * 128, gstage + 8192);
                            } else {
                                tma_st2d(&sKh, colbase, mt * 128, gstage);
                                tma_st2d(&sKl, colbase, mt * 128, gstage + 8192);
                            }
                            TMA_ST_COMMIT();
                        }
                    } else {
#pragma unroll
                        for (int c = 0; c < 32; c++) {
                            __nv_bfloat16 h, l;
                            split1(__uint_as_float(r[c]), h, l);
                            sh_[c * 128 + growIdx] = h;
                            sl_[c * 128 + growIdx] = l;
                        }
                        FENCE_ASYNC();
                        BARG(gbar);
                        if (gtid == 0) {
                            const int mloc0 = (mt * 128) & (LNc - 1);
                            const int y = (mt >> 4) * 512 + ni * 128 + ch * 32;
                            tma_st2d(&sVh, mloc0, y, gstage);
                            tma_st2d(&sVl, mloc0, y, gstage + 8192);
                            TMA_ST_COMMIT();
                        }
                    }
                }
            }
            if (gtid == 0) TMA_ST_WAIT0();
        }
        __syncthreads();
        if (tid == 0) {
            __threadfence();
            atomicExch(&(halfN ? g_f_vt : g_f_qk)[mt], 1);
        }
    } else if (mode == 1) {
        const int idx = bid - 512;
        const int quarter = idx & 3, lb = (idx >> 2) & 15, bh = idx >> 6;
        int mbs[4], nband = 0;
        for (int t = 0; t < 4; t++) {
            const int mb = quarter * 4 + t;
            const int d = lb - mb;
            if (d >= 0 && d <= 8) mbs[nband++] = mb;
        }
        const int S = nband * 4;
        if (tid == 256 && nband > 0) {
            // wait for q row-block lb and all needed k row-blocks
            spin_ge(&g_f_qk[bh * 16 + lb], 1);
            for (int t = 0; t < nband; t++) spin_ge(&g_f_qk[bh * 16 + mbs[t]], 1);
            __threadfence();
            auto issueQ = [&](int s) {
                const int b = s & 1;
                EXPECT_TX(B_XF(b), 32768);
                tma2d(XB(b),         &mqh, s * 64, bh * 2048 + lb * 128, B_XF(b));
                tma2d(XB(b) + 16384, &mql, s * 64, bh * 2048 + lb * 128, B_XF(b));
            };
            auto issueK = [&](int g) {
                const int b = g & 3;
                const int mb = mbs[g % nband], s = g / nband;
                EXPECT_TX(B_WF(b), 32768);
                tma2d(WR(b),         &mkh, s * 64, bh * 2048 + mb * 128, B_WF(b));
                tma2d(WR(b) + 16384, &mkl, s * 64, bh * 2048 + mb * 128, B_WF(b));
            };
            issueQ(0); issueQ(1);
            const int pre = (S < 4) ? S : 4;
            for (int g = 0; g < pre; g++) issueK(g);
            int phXF[2] = {0, 0}, phXE[2] = {0, 0};
            int phWF[4] = {0, 0, 0, 0}, phWE[4] = {0, 0, 0, 0};
            for (int g = 0; g < S; g++) {
                const int s = g / nband, ti = g % nband, wb = g & 3, xbuf = s & 1;
                if (ti == 0) { MBAR_WAIT(B_XF(xbuf), phXF[xbuf]); phXF[xbuf] ^= 1; }
                MBAR_WAIT(B_WF(wb), phWF[wb]); phWF[wb] ^= 1;
                const uint64_t ah_ = mkdesc(XB(xbuf));
                const uint64_t al_ = mkdesc(XB(xbuf) + 16384);
                const uint64_t bh_ = mkdesc(WR(wb));
                const uint64_t bl_ = mkdesc(WR(wb) + 16384);
                const uint32_t dacc = tmem + ti * 128;
#pragma unroll
                for (int ks = 0; ks < 4; ks++) {
                    mma_bf16(dacc, ah_ + ks * 2, bh_ + ks * 2, IDESC_N128, (s > 0 || ks > 0) ? 1u : 0u);
                    mma_bf16(dacc, ah_ + ks * 2, bl_ + ks * 2, IDESC_N128, 1u);
                    mma_bf16(dacc, al_ + ks * 2, bh_ + ks * 2, IDESC_N128, 1u);
                }
                TC_COMMIT(B_WE(wb));
                if (ti == nband - 1) TC_COMMIT(B_XE(xbuf));
                if (s == 3) TC_COMMIT(B_AF(ti));
                if (g + 4 < S) { MBAR_WAIT(B_WE(wb), phWE[wb]); phWE[wb] ^= 1; issueK(g + 4); }
                if (ti == nband - 1 && s + 2 < 4) {
                    MBAR_WAIT(B_XE(xbuf), phXE[xbuf]); phXE[xbuf] ^= 1;
                    issueQ(s + 2);
                }
            }
        }
        if (tid < 256) {
            {   // zero tiles for this quarter
                const float4 z = make_float4(0.f, 0.f, 0.f, 0.f);
                for (int t = 0; t < 4; t++) {
                    const int mb = quarter * 4 + t;
                    const int d = lb - mb;
                    if (d >= 0 && d <= 8) continue;
                    float* base = score + ((size_t)bh * LNc + (size_t)lb * 128) * LNc + mb * 128;
#pragma unroll 4
                    for (int i = 0; i < 16; i++) {
                        const int e = i * 256 + tid;
                        const int row = e >> 5, c4 = e & 31;
                        *((float4*)(base + (size_t)row * LNc) + c4) = z;
                    }
                }
            }
            if (nband > 0) {
                const int l = lb * 128 + growIdx;
                const float gpl = exp2f((float)(l + 1) * LOG2G);
                const float scale = 0.0625f / ((1.0f - gpl) * 10.0f);
                for (int ti = 0; ti < nband; ti++) {
                    const int mb = mbs[ti];
                    const int diag = lb - mb;
                    MBAR_WAIT(B_AF(ti), 0);
                    TC_FENCE_AFTER();
#pragma unroll 1
                    for (int ch = grp; ch < 4; ch += 2) {
                        uint32_t r[32];
                        TC_LD_X32(r, tmem + ti * 128 + ch * 32);
                        TC_WAIT_LD();
                        const int m0 = mb * 128 + ch * 32;
                        float v[32];
                        if (m0 > l) {
#pragma unroll
                            for (int c = 0; c < 32; c++) v[c] = 0.f;
                        } else {
                            float w = exp2f((float)(l - m0) * LOG2G) * scale;
#pragma unroll
                            for (int c = 0; c < 32; c++) {
                                v[c] = (m0 + c <= l) ? __uint_as_float(r[c]) * w : 0.f;
                                w *= GINVf;
                            }
                        }
                        uint32_t hi[16], lo[16];
#pragma unroll
                        for (int c = 0; c < 32; c += 2)
                            split2(v[c], v[c + 1], hi[c >> 1], lo[c >> 1]);
                        const int tile9 = (bh * 16 + lb) * 9 + diag;
                        const size_t sbase = ((size_t)tile9 * 128 + growIdx) * 128 + ch * 32;
#pragma unroll
                        for (int q4 = 0; q4 < 4; q4++) {
                            *(uint4*)&g_s_hi[sbase + q4 * 8] = ((uint4*)hi)[q4];
                            *(uint4*)&g_s_lo[sbase + q4 * 8] = ((uint4*)lo)[q4];
                        }
                        if (gtid == 0) TMA_ST_WAIT0();
                        BARG(gbar);
#pragma unroll
                        for (int c4 = 0; c4 < 32; c4 += 4) {
                            uint32_t byte = growIdx * 128 + c4 * 4;
                            uint32_t sw = byte ^ ((byte >> 3) & 0x70);
                            *(float4*)(smem + STAGE_OFF + grp * 16384 + sw) =
                                make_float4(v[c4], v[c4 + 1], v[c4 + 2], v[c4 + 3]);
                        }
                        FENCE_ASYNC();
                        BARG(gbar);
                        if (gtid == 0) {
                            tma_st2d(&sSc, m0, bh * 2048 + lb * 128, gstage);
                            TMA_ST_COMMIT();
                        }
                    }
                }
                if (gtid == 0) TMA_ST_WAIT0();
            }
        }
        __syncthreads();
        if (tid == 0) {
            __threadfence();
            atomicAdd(&g_f_s[bh * 16 + lb], 1);
        }
    } else {
        const int idx = bid - 1536;
        const int half = idx & 1, lb = (idx >> 1) & 15, bh = idx >> 5;
        const int dmax = lb < 8 ? lb : 8, mb0 = lb - dmax;
        const int nst = (dmax + 1) * 2;

        if (tid == 256) {
            // wait for the s band of this row-block and needed v^T columns
            spin_ge(&g_f_s[bh * 16 + lb], 4);
            for (int m = mb0; m <= lb; m++) spin_ge(&g_f_vt[bh * 16 + m], 1);
            __threadfence();
            auto issueStg = [&](int s, int b) {
                const int xa = (s & 1) * 64;
                const int ya = ((bh * 16 + lb) * 9 + (dmax - (s >> 1))) * 128;
                const int xb2 = mb0 * 128 + s * 64;
                const int yb = bh * 512 + half * 256;
                const uint32_t dst = smem_base + RING2_OFF + b * STG2;
                EXPECT_TX(B_WF(b), STG2);
                tma2d(dst,         &msh, xa, ya, B_WF(b));
                tma2d(dst + 16384, &msl, xa, ya, B_WF(b));
                tma2d(dst + 32768, &mvh, xb2, yb, B_WF(b));
                tma2d(dst + 65536, &mvl, xb2, yb, B_WF(b));
            };
            const int pre = nst < 2 ? nst : 2;
            for (int s = 0; s < pre; s++) issueStg(s, s);
            int phF[2] = {0, 0}, phE[2] = {0, 0};
            for (int s = 0; s < nst; s++) {
                const int b = s & 1;
                MBAR_WAIT(B_WF(b), phF[b]); phF[b] ^= 1;
                const uint32_t stg = smem_base + RING2_OFF + b * STG2;
                const uint64_t ah  = mkdesc(stg);
                const uint64_t al  = mkdesc(stg + 16384);
                const uint64_t bhd = mkdesc(stg + 32768);
                const uint64_t bld = mkdesc(stg + 65536);
#pragma unroll
                for (int ks = 0; ks < 4; ks++) {
                    mma_bf16(tmem, ah + ks * 2, bhd + ks * 2, IDESC_N256, (s > 0 || ks > 0) ? 1u : 0u);
                    mma_bf16(tmem, ah + ks * 2, bld + ks * 2, IDESC_N256, 1u);
                    mma_bf16(tmem, al + ks * 2, bhd + ks * 2, IDESC_N256, 1u);
                }
                TC_COMMIT(B_WE(b));
                if (s + 2 < nst) {
                    MBAR_WAIT(B_WE(b), phE[b]); phE[b] ^= 1;
                    issueStg(s + 2, b);
                }
            }
            TC_COMMIT(B_AF(0));
        }
        if (tid < 256) {
            MBAR_WAIT(B_AF(0), 0);
            TC_FENCE_AFTER();
#pragma unroll 1
            for (int ch = grp; ch < 8; ch += 2) {
                uint32_t r[32];
                TC_LD_X32(r, tmem + ch * 32);
                TC_WAIT_LD();
                if (gtid == 0) TMA_ST_WAIT0();
                BARG(gbar);
#pragma unroll
                for (int c4 = 0; c4 < 32; c4 += 4) {
                    uint32_t byte = growIdx * 128 + c4 * 4;
                    uint32_t sw = byte ^ ((byte >> 3) & 0x70);
                    *(float4*)(smem + STAGE_OFF + grp * 16384 + sw) = make_float4(
                        __uint_as_float(r[c4]),     __uint_as_float(r[c4 + 1]),
                        __uint_as_float(r[c4 + 2]), __uint_as_float(r[c4 + 3]));
                }
                FENCE_ASYNC();
                BARG(gbar);
                if (gtid == 0) {
                    tma_st2d(&sVt, half * 256 + ch * 32, bh * 2048 + lb * 128, gstage);
                    TMA_ST_COMMIT();
                }
            }
            if (gtid == 0) TMA_ST_WAIT0();
        }
        __syncthreads();
    }

    __syncthreads();
    if (wid == 0) {
        TC_RELINQ();
        TC_DEALLOC(tmem, 512);
    }

#else
    // ---------------- correct (slow) SIMT fallback ---------------------------
    if (mode == 0) {
        const int mt = bid >> 1, halfN = bid & 1;
        if (tid < 256) {
            for (int ni = 0; ni < 4; ni++) {
                const int nb = halfN * 4 + ni;
                if (nb < 4) {
                    const bool isQ = nb < 2;
                    const int colbase = (isQ ? nb : nb - 2) * 128;
                    for (int e = tid; e < 128 * 64; e += 256) {
                        const int i = e >> 6, j = (e & 63) * 2;
                        float a0 = 0.f, a1 = 0.f;
                        const size_t ra = (size_t)(mt * 128 + i) * 256;
                        const size_t rb0 = (size_t)(nb * 128 + j) * 256;
#pragma unroll 4
                        for (int k = 0; k < 256; k++) {
                            float xv = joinf(g_x_hi, g_x_lo, ra + k);
                            a0 += xv * joinf(g_w_hi, g_w_lo, rb0 + k);
                            a1 += xv * joinf(g_w_hi, g_w_lo, rb0 + 256 + k);
                        }
                        const int l = (mt * 128 + i) & (LNc - 1);
                        const int col = colbase + j;
                        float theta = exp2f(-(float)(col >> 1) * (13.287712379549449f / 127.0f));
                        float sn, cs;
                        sincosf((float)l * theta, &sn, &cs);
                        float ne, no;
                        if (isQ) { ne = a0 * cs - a1 * sn; no = a1 * cs + a0 * sn; }
                        else     { ne = a0 * cs + a1 * sn; no = a1 * cs - a0 * sn; }
                        __nv_bfloat16 h0, l0, h1, l1;
                        split1(ne, h0, l0); split1(no, h1, l1);
                        __nv_bfloat16* dh = isQ ? g_q_hi : g_k_hi;
                        __nv_bfloat16* dl = isQ ? g_q_lo : g_k_lo;
                        const size_t bidx = (size_t)(mt * 128 + i) * 256 + col;
                        dh[bidx] = h0; dh[bidx + 1] = h1;
                        dl[bidx] = l0; dl[bidx + 1] = l1;
                    }
                } else {
                    for (int e = tid; e < 128 * 128; e += 256) {
                        const int i = e >> 7, j = e & 127;
                        float a0 = 0.f;
                        const size_t ra = (size_t)(mt * 128 + i) * 256;
                        const size_t rb = (size_t)(nb * 128 + j) * 256;
#pragma unroll 4
                        for (int k = 0; k < 256; k++)
                            a0 += joinf(g_x_hi, g_x_lo, ra + k) * joinf(g_w_hi, g_w_lo, rb + k);
                        const int mrow = mt * 128 + i;
                        const int bhv = mrow >> 11, mloc = mrow & (LNc - 1);
                        __nv_bfloat16 h, l;
                        split1(a0, h, l);
                        const size_t idx2 = ((size_t)bhv * 512 + (nb - 4) * 128 + j) * 2048 + mloc;
                        g_vt_hi[idx2] = h; g_vt_lo[idx2] = l;
                    }
                }
            }
        }
        __syncthreads();
        if (tid == 0) { __threadfence(); atomicExch(&(halfN ? g_f_vt : g_f_qk)[mt], 1); }
    } else if (mode == 1) {
        const int idx = bid - 512;
        const int quarter = idx & 3, lb = (idx >> 2) & 15, bh = idx >> 6;
        if (tid == 0) {
            spin_ge(&g_f_qk[bh * 16 + lb], 1);
            for (int t = 0; t < 4; t++) {
                const int mb = quarter * 4 + t;
                const int d = lb - mb;
                if (d >= 0 && d <= 8) spin_ge(&g_f_qk[bh * 16 + mb], 1);
            }
            __threadfence();
        }
        __syncthreads();
        if (tid < 256) {
            for (int t = 0; t < 4; t++) {
                const int mb = quarter * 4 + t;
                const int d = lb - mb;
                if (d < 0 || d > 8) {
                    float* base = score + ((size_t)bh * LNc + (size_t)lb * 128) * LNc + mb * 128;
                    for (int e = tid; e < 128 * 128; e += 256) {
                        const int i = e >> 7, j = e & 127;
                        base[(size_t)i * LNc + j] = 0.f;
                    }
                    continue;
                }
                for (int e = tid; e < 128 * 128; e += 256) {
                    const int i = e >> 7, j = e & 127;
                    float acc = 0.f;
                    const size_t ra = ((size_t)bh * 2048 + lb * 128 + i) * 256;
                    const size_t rb = ((size_t)bh * 2048 + mb * 128 + j) * 256;
#pragma unroll 4
                    for (int k = 0; k < 256; k++)
                        acc += joinf(g_q_hi, g_q_lo, ra + k) * joinf(g_k_hi, g_k_lo, rb + k);
                    const int l = lb * 128 + i, m = mb * 128 + j;
                    const float gpl = exp2f((float)(l + 1) * LOG2G);
                    const float scale = 0.0625f / ((1.0f - gpl) * 10.0f);
                    float w = (m <= l) ? exp2f((float)(l - m) * LOG2G) * scale : 0.f;
                    float v = acc * w;
                    score[((size_t)bh * LNc + l) * LNc + m] = v;
                    __nv_bfloat16 h, lo_;
                    split1(v, h, lo_);
                    const size_t sbase = ((size_t)((bh * 16 + lb) * 9 + d) * 128 + i) * 128 + j;
                    g_s_hi[sbase] = h; g_s_lo[sbase] = lo_;
                }
            }
        }
        __syncthreads();
        if (tid == 0) { __threadfence(); atomicAdd(&g_f_s[bh * 16 + lb], 1); }
    } else {
        const int idx = bid - 1536;
        const int half = idx & 1, lb = (idx >> 1) & 15, bh = idx >> 5;
        const int dmax = lb < 8 ? lb : 8, mb0 = lb - dmax;
        const int Kl = (dmax + 1) * 128;
        if (tid == 0) {
            spin_ge(&g_f_s[bh * 16 + lb], 4);
            for (int m = mb0; m <= lb; m++) spin_ge(&g_f_vt[bh * 16 + m], 1);
            __threadfence();
        }
        __syncthreads();
        if (tid < 256) {
            for (int e = tid; e < 128 * 256; e += 256) {
                const int i = e >> 8, j = e & 255;
                float acc = 0.f;
                const size_t rb = ((size_t)bh * 512 + half * 256 + j) * 2048 + mb0 * 128;
#pragma unroll 4
                for (int k = 0; k < Kl; k++) {
                    const size_t ra = ((size_t)((bh * 16 + lb) * 9 + (dmax - (k >> 7))) * 128 + i) * 128 + (k & 127);
                    acc += joinf(g_s_hi, g_s_lo, ra) * joinf(g_vt_hi, g_vt_lo, rb + k);
                }
                vtout[((size_t)bh * LNc + lb * 128 + i) * VDc + half * 256 + j] = acc;
            }
        }
    }
#endif
}

// ---------------- host ------------------------------------------------------
typedef CUresult (*EncodeFn)(CUtensorMap*, CUtensorMapDataType, cuuint32_t, void*,
                             const cuuint64_t*, const cuuint64_t*, const cuuint32_t*,
                             const cuuint32_t*, CUtensorMapInterleave, CUtensorMapSwizzle,
                             CUtensorMapL2promotion, CUtensorMapFloatOOBfill);

static void make_map(EncodeFn fn, CUtensorMap* m, void* base, CUtensorMapDataType dt,
                     uint64_t d0, uint64_t d1, uint64_t strideB,
                     uint32_t box0, uint32_t box1, CUtensorMapSwizzle sw) {
    cuuint64_t dims[2]    = {d0, d1};
    cuuint64_t strides[1] = {strideB};
    cuuint32_t box[2]     = {box0, box1};
    cuuint32_t es[2]      = {1, 1};
    fn(m, dt, 2, base, dims, strides, box, es,
       CU_TENSOR_MAP_INTERLEAVE_NONE, sw,
       CU_TENSOR_MAP_L2_PROMOTION_L2_128B, CU_TENSOR_MAP_FLOAT_OOB_FILL_NONE);
}

extern "C" void kernel_launch(void* const* d_in, const int* in_sizes, int n_in,
                              void* d_out, int out_size) {
    const float* X  = (const float*)d_in[0];
    const float* WQ = (const float*)d_in[1];
    const float* WK = (const float*)d_in[2];
    const float* WV = (const float*)d_in[3];

    float* out       = (float*)d_out;
    float* out_vt    = out;
    float* out_score = out + (size_t)BHc * LNc * VDc;

    EncodeFn enc = nullptr;
    cudaDriverEntryPointQueryResult qr;
    cudaGetDriverEntryPoint("cuTensorMapEncodeTiled", (void**)&enc,
                            cudaEnableDefault, &qr);

    void *xh, *xl, *wh, *wl, *qh, *ql, *kh, *kl, *vh, *vl, *sh, *sl;
    cudaGetSymbolAddress(&xh, g_x_hi);  cudaGetSymbolAddress(&xl, g_x_lo);
    cudaGetSymbolAddress(&wh, g_w_hi);  cudaGetSymbolAddress(&wl, g_w_lo);
    cudaGetSymbolAddress(&qh, g_q_hi);  cudaGetSymbolAddress(&ql, g_q_lo);
    cudaGetSymbolAddress(&kh, g_k_hi);  cudaGetSymbolAddress(&kl, g_k_lo);
    cudaGetSymbolAddress(&vh, g_vt_hi); cudaGetSymbolAddress(&vl, g_vt_lo);
    cudaGetSymbolAddress(&sh, g_s_hi);  cudaGetSymbolAddress(&sl, g_s_lo);

    const CUtensorMapDataType BF = CU_TENSOR_MAP_DATA_TYPE_BFLOAT16;
    const CUtensorMapDataType F32 = CU_TENSOR_MAP_DATA_TYPE_FLOAT32;
    const CUtensorMapSwizzle SW = CU_TENSOR_MAP_SWIZZLE_128B;
    const CUtensorMapSwizzle NO = CU_TENSOR_MAP_SWIZZLE_NONE;

    CUtensorMap mxh, mxl, mwh, mwl, mqh, mql, mkh, mkl, mvh, mvl, msh, msl;
    make_map(enc, &mxh, xh, BF, 256, 32768, 512, 64, 128, SW);
    make_map(enc, &mxl, xl, BF, 256, 32768, 512, 64, 128, SW);
    make_map(enc, &mwh, wh, BF, 256, 1024, 512, 64, 128, SW);
    make_map(enc, &mwl, wl, BF, 256, 1024, 512, 64, 128, SW);
    make_map(enc, &mqh, qh, BF, 256, 32768, 512, 64, 128, SW);
    make_map(enc, &mql, ql, BF, 256, 32768, 512, 64, 128, SW);
    make_map(enc, &mkh, kh, BF, 256, 32768, 512, 64, 128, SW);
    make_map(enc, &mkl, kl, BF, 256, 32768, 512, 64, 128, SW);
    make_map(enc, &mvh, vh, BF, 2048, 8192, 4096, 64, 256, SW);
    make_map(enc, &mvl, vl, BF, 2048, 8192, 4096, 64, 256, SW);
    make_map(enc, &msh, sh, BF, 128, 294912, 256, 64, 128, SW);
    make_map(enc, &msl, sl, BF, 128, 294912, 256, 64, 128, SW);
    CUtensorMap sQh, sQl, sKh, sKl, sVh, sVl, sSc, sVt;
    make_map(enc, &sQh, qh, BF, 256, 32768, 512, 32, 128, NO);
    make_map(enc, &sQl, ql, BF, 256, 32768, 512, 32, 128, NO);
    make_map(enc, &sKh, kh, BF, 256, 32768, 512, 32, 128, NO);
    make_map(enc, &sKl, kl, BF, 256, 32768, 512, 32, 128, NO);
    make_map(enc, &sVh, vh, BF, 2048, 8192, 4096, 128, 32, NO);
    make_map(enc, &sVl, vl, BF, 2048, 8192, 4096, 128, 32, NO);
    make_map(enc, &sSc, out_score, F32, 2048, 32768, 8192, 32, 128, SW);
    make_map(enc, &sVt, out_vt,    F32, 512, 32768, 2048, 32, 128, SW);

    cudaFuncSetAttribute(mega, cudaFuncAttributeMaxDynamicSharedMemorySize, SMEM_TOTAL);

    prep_k<<<10241, 256>>>(X, WQ, WK, WV);
    mega<<<2048, 384, SMEM_TOTAL>>>(mxh, mxl, mwh, mwl,
                                    mqh, mql, mkh, mkl,
                                    msh, msl, mvh, mvl,
                                    sQh, sQl, sKh, sKl, sVh, sVl,
                                    sSc, sVt,
                                    out_score, out_vt);
}